// round 12
// baseline (speedup 1.0000x reference)
#include <cuda_runtime.h>
#include <cuda_fp16.h>
#include <cstdint>

typedef unsigned int u32;

#define B_TOT   4096
#define K_STEPS 512
#define M_ROWS  32
#define THREADS 320

#define H16_P 136
#define X16_P 40
#define HW_P  136
#define WIH_P 40
#define WHN_P 136

// dynamic smem byte offsets
#define HB0_OFF   0        // h buf0: 32*136*2 = 8704
#define HB1_OFF   8704
#define X16_OFF   17408    // 32*40*2 = 2560
#define WIH_OFF   19968    // 3*128*40*2 = 30720
#define WHN_OFF   50688    // 128*136*2 = 34816 (W_hh n-gate, ldsm layout)
#define HW_OFF    85504    // 8*136*2 = 2176
#define F32_OFF   87680    // floats
#define SMEM_TOTAL 90112

__device__ __forceinline__ u32 packh2(float a, float b) {
    __half2 h = __floats2half2_rn(a, b);
    return *(u32*)&h;
}
__device__ __forceinline__ float tanh_fast(float x) {
    float r; asm("tanh.approx.f32 %0,%1;" : "=f"(r) : "f"(x)); return r;
}
__device__ __forceinline__ float sig_fast(float x) {
    return fmaf(tanh_fast(0.5f * x), 0.5f, 0.5f);
}
__device__ __forceinline__ float sigmoid_exact(float x) {
    x = fminf(fmaxf(x, -30.f), 30.f);
    return __fdividef(1.f, 1.f + __expf(-x));
}
__device__ __forceinline__ void rhs5(const float* y, const float* th, float* d) {
    float f1 = th[0] * y[0] - th[4] * y[1];
    float f2 = th[1] * y[1] - th[5] * y[2];
    float f3 = th[2] * y[2] - th[6] * y[3];
    float f4 = th[3] * y[3] - th[7] * y[4];
    d[0] = -f1; d[1] = f1 - f2; d[2] = f2 - f3; d[3] = f3 - f4; d[4] = f4;
}
__device__ __forceinline__ void mma4(float* c, const u32* a, u32 b0, u32 b1) {
    asm volatile(
        "mma.sync.aligned.m16n8k16.row.col.f32.f16.f16.f32 "
        "{%0,%1,%2,%3},{%4,%5,%6,%7},{%8,%9},{%0,%1,%2,%3};"
        : "+f"(c[0]), "+f"(c[1]), "+f"(c[2]), "+f"(c[3])
        : "r"(a[0]), "r"(a[1]), "r"(a[2]), "r"(a[3]), "r"(b0), "r"(b1));
}
__device__ __forceinline__ void ldsm4(u32* a, u32 sa) {
    asm volatile("ldmatrix.sync.aligned.m8n8.x4.shared.b16 {%0,%1,%2,%3},[%4];"
        : "=r"(a[0]), "=r"(a[1]), "=r"(a[2]), "=r"(a[3]) : "r"(sa));
}

__global__ void __launch_bounds__(THREADS, 1)
rnn_main(const float* __restrict__ y0,
         const float* __restrict__ u_seq,
         const float* __restrict__ dt_seq,
         const float* __restrict__ lift_W,
         const float* __restrict__ lift_b,
         const float* __restrict__ W_ih,
         const float* __restrict__ W_hh,
         const float* __restrict__ b_ih,
         const float* __restrict__ b_hh,
         const float* __restrict__ head_W,
         const float* __restrict__ head_b,
         const float* __restrict__ ujump,
         float* __restrict__ y_out,
         float* __restrict__ theta_out) {
    extern __shared__ char smc[];
    __half* hbuf0 = (__half*)(smc + HB0_OFF);
    __half* hbuf1 = (__half*)(smc + HB1_OFF);
    __half* x16   = (__half*)(smc + X16_OFF);
    __half* wih16 = (__half*)(smc + WIH_OFF);
    __half* whn16 = (__half*)(smc + WHN_OFF);
    __half* hW16  = (__half*)(smc + HW_OFF);
    float*  fm    = (float*)(smc + F32_OFF);
    float* lW_s = fm;          // 256
    float* lb_s = fm + 256;    // 32
    float* hb_s = fm + 288;    // 8
    float* uj_s = fm + 296;    // 16
    float* th_s = fm + 312;    // 256

    const int t = threadIdx.x, w = t >> 5, lane = t & 31;
    const int qr = lane >> 2, qc = lane & 3;
    const int R0 = blockIdx.x * M_ROWS;
    const int lm = lane >> 3;
    const bool is_mma = (w < 8);

    // ---------------- prologue: smem staging (all warps) ----------------
    for (int i = t; i < 32 * H16_P / 2; i += THREADS) {
        ((u32*)hbuf0)[i] = 0;
        ((u32*)hbuf1)[i] = 0;
    }
    for (int i = t; i < 3 * 128 * 32; i += THREADS) {
        int g = i >> 12, rem = i & 4095, jj = rem >> 5, l = rem & 31;
        wih16[g * 128 * WIH_P + jj * WIH_P + l] = __float2half_rn(W_ih[i]);
    }
    for (int i = t; i < 128 * 128; i += THREADS) {
        int jj = i >> 7, kk = i & 127;
        whn16[jj * WHN_P + kk] = __float2half_rn(W_hh[(256 + jj) * 128 + kk]);
    }
    for (int i = t; i < 1024; i += THREADS) {
        int c = i >> 7, kk = i & 127;
        hW16[c * HW_P + kk] = __float2half_rn(head_W[i]);
    }
    for (int i = t; i < 256; i += THREADS) lW_s[i] = lift_W[i];
    if (t < 32) lb_s[t] = lift_b[t];
    if (t < 8)  hb_s[t] = head_b[t];
    if (t < 15) uj_s[t] = ujump[t];

    u32 smb;
    asm("{ .reg .u64 tt; cvta.to.shared.u64 tt, %1; cvt.u32.u64 %0, tt; }"
        : "=r"(smb) : "l"((const void*)smc));

    // ---------------- MMA-warp constants ----------------
    const int wj = (w & 7) * 16;
    const int j_lo = wj + qr, j_hi = j_lo + 8;
    u32 agh[2][8][4];     // r,z gate W_hh frags in regs; n-gate via ldsm
    float bR0 = 0, bR1 = 0, bZ0 = 0, bZ1 = 0, bNI0 = 0, bNI1 = 0, bNH0 = 0, bNH1 = 0;
    if (is_mma) {
        #pragma unroll
        for (int g = 0; g < 2; ++g)
            #pragma unroll
            for (int s = 0; s < 8; ++s) {
                const float* p = W_hh + (g * 128 + j_lo) * 128 + 16 * s + qc * 2;
                agh[g][s][0] = packh2(p[0], p[1]);
                agh[g][s][1] = packh2(p[1024], p[1025]);
                agh[g][s][2] = packh2(p[8], p[9]);
                agh[g][s][3] = packh2(p[1032], p[1033]);
            }
        bR0  = b_ih[j_lo] + b_hh[j_lo];
        bR1  = b_ih[j_hi] + b_hh[j_hi];
        bZ0  = b_ih[128 + j_lo] + b_hh[128 + j_lo];
        bZ1  = b_ih[128 + j_hi] + b_hh[128 + j_hi];
        bNI0 = b_ih[256 + j_lo]; bNI1 = b_ih[256 + j_hi];
        bNH0 = b_hh[256 + j_lo]; bNH1 = b_hh[256 + j_hi];
    }
    const u32 wih_lane = smb + WIH_OFF +
        (u32)((wj + (lm & 1) * 8 + (lane & 7)) * WIH_P + (lm >> 1) * 8) * 2u;
    const u32 whn_lane = smb + WHN_OFF +
        (u32)((wj + (lm & 1) * 8 + (lane & 7)) * WHN_P + (lm >> 1) * 8) * 2u;

    // ---------------- tail-warp state (w8/w9) ----------------
    const int wt = w - 8;                       // 0/1 (tail only)
    const int trow = (wt << 4) + (lane & 15);   // this lane's batch row
    const u32 head_row_off =
        (u32)(((wt << 4) + (lm & 1) * 8 + (lane & 7)) * H16_P + (lm >> 1) * 8) * 2u;
    const int lbase = lane & 16;                // l range: 0-15 or 16-31
    float y[5] = {0, 0, 0, 0, 0};
    float pre[16];
    float uc0 = 0, uc1 = 0, uc2 = 0, dtc = 0;
    float un0 = 0, un1 = 0, un2 = 0, dtn = 0;
    if (!is_mma) {
        #pragma unroll
        for (int i = 0; i < 5; ++i) y[i] = y0[(R0 + trow) * 5 + i] + 0.01f;
        const float* up = u_seq + ((size_t)(R0 + trow) * K_STEPS) * 3;
        uc0 = up[0]; uc1 = up[1]; uc2 = up[2];
        dtc = dt_seq[(size_t)(R0 + trow) * K_STEPS];
    }

    float cR[4][4], cZ[4][4], cNI[4][4], cNH[4][4];
    float hp_[4][4] = {{0,0,0,0},{0,0,0,0},{0,0,0,0},{0,0,0,0}};

    auto init_accs = [&]() {
        #pragma unroll
        for (int nt = 0; nt < 4; ++nt) {
            cR[nt][0] = bR0;  cR[nt][1] = bR0;  cR[nt][2] = bR1;  cR[nt][3] = bR1;
            cZ[nt][0] = bZ0;  cZ[nt][1] = bZ0;  cZ[nt][2] = bZ1;  cZ[nt][3] = bZ1;
            cNI[nt][0] = bNI0; cNI[nt][1] = bNI0; cNI[nt][2] = bNI1; cNI[nt][3] = bNI1;
            cNH[nt][0] = bNH0; cNH[nt][1] = bNH0; cNH[nt][2] = bNH1; cNH[nt][3] = bNH1;
        }
    };
    auto do_gh = [&](const __half* hb) {
        #pragma unroll
        for (int s = 0; s < 8; ++s) {
            u32 aN[4];
            ldsm4(aN, whn_lane + (u32)s * 32u);
            #pragma unroll
            for (int nt = 0; nt < 4; ++nt) {
                const __half* hp = hb + (qr + 8 * nt) * H16_P + 16 * s + qc * 2;
                u32 b0 = *(const u32*)hp;
                u32 b1 = *(const u32*)(hp + 8);
                mma4(cR[nt],  agh[0][s], b0, b1);
                mma4(cZ[nt],  agh[1][s], b0, b1);
                mma4(cNH[nt], aN, b0, b1);
            }
        }
    };
    auto do_gi = [&]() {
        #pragma unroll
        for (int s = 0; s < 2; ++s) {
            u32 aR_[4], aZ_[4], aN_[4];
            ldsm4(aR_, wih_lane + (u32)s * 32u);
            ldsm4(aZ_, wih_lane + 10240u + (u32)s * 32u);
            ldsm4(aN_, wih_lane + 20480u + (u32)s * 32u);
            #pragma unroll
            for (int nt = 0; nt < 4; ++nt) {
                const __half* xp = x16 + (qr + 8 * nt) * X16_P + 16 * s + qc * 2;
                u32 b0 = *(const u32*)xp;
                u32 b1 = *(const u32*)(xp + 8);
                mma4(cR[nt],  aR_, b0, b1);
                mma4(cZ[nt],  aZ_, b0, b1);
                mma4(cNI[nt], aN_, b0, b1);
            }
        }
    };
    auto epilogue = [&](__half* hb) {
        #pragma unroll
        for (int nt = 0; nt < 4; ++nt) {
            int r0 = qc * 2 + 8 * nt;
            float hn[4];
            #pragma unroll
            for (int c = 0; c < 4; ++c) {
                float gr = sig_fast(cR[nt][c]);
                float gz = sig_fast(cZ[nt][c]);
                float gn = tanh_fast(fmaf(gr, cNH[nt][c], cNI[nt][c]));
                hn[c] = (1.f - gz) * gn + gz * hp_[nt][c];
                hp_[nt][c] = hn[c];
            }
            hb[r0 * H16_P + j_lo]       = __float2half_rn(hn[0]);
            hb[(r0 + 1) * H16_P + j_lo] = __float2half_rn(hn[1]);
            hb[r0 * H16_P + j_hi]       = __float2half_rn(hn[2]);
            hb[(r0 + 1) * H16_P + j_hi] = __float2half_rn(hn[3]);
        }
    };

    __syncthreads();
    // pre-loop: tail computes x(0) fully; MMA warps then build gates(0)
    if (!is_mma) {
        float f[8];
        f[0] = uc0; f[1] = uc1; f[2] = uc2;
        #pragma unroll
        for (int i = 0; i < 5; ++i) f[3 + i] = y[i];
        #pragma unroll
        for (int i = 0; i < 8; ++i) {
            int l0 = lbase + 2 * i;
            float a0 = lb_s[l0], a1 = lb_s[l0 + 1];
            #pragma unroll
            for (int q = 0; q < 8; ++q) {
                a0 = fmaf(lW_s[l0 * 8 + q], f[q], a0);
                a1 = fmaf(lW_s[(l0 + 1) * 8 + q], f[q], a1);
            }
            *(u32*)&x16[trow * X16_P + l0] =
                packh2(a0 * sig_fast(a0), a1 * sig_fast(a1));
        }
    }
    __syncthreads();
    if (is_mma) { init_accs(); do_gi(); }   // gh(0) contributes 0 (h=0)

    // ---------------- main loop: 2 barriers/step ----------------
    for (int k = 0; k < K_STEPS; ++k) {
        __half* hb_cur = (k & 1) ? hbuf1 : hbuf0;
        // phase 1
        if (is_mma) {
            epilogue(hb_cur);               // h(k)
        } else if (k + 1 < K_STEPS) {
            const float* up = u_seq + ((size_t)(R0 + trow) * K_STEPS + (k + 1)) * 3;
            un0 = up[0]; un1 = up[1]; un2 = up[2];
            dtn = dt_seq[(size_t)(R0 + trow) * K_STEPS + (k + 1)];
            #pragma unroll
            for (int i = 0; i < 16; ++i) {
                int l = lbase + i;
                float a = lb_s[l];
                a = fmaf(lW_s[l * 8 + 0], un0, a);
                a = fmaf(lW_s[l * 8 + 1], un1, a);
                a = fmaf(lW_s[l * 8 + 2], un2, a);
                pre[i] = a;
            }
        }
        __syncthreads();                    // A: h(k) visible

        // phase 2
        if (is_mma) {
            if (k + 1 < K_STEPS) { init_accs(); do_gh(hb_cur); }
        } else {
            // head(k): one 16-row tile per tail warp
            float cH[4];
            cH[0] = hb_s[qc * 2]; cH[1] = hb_s[qc * 2 + 1];
            cH[2] = cH[0];        cH[3] = cH[1];
            u32 a_lane = smb + ((k & 1) ? HB1_OFF : HB0_OFF) + head_row_off;
            #pragma unroll
            for (int s = 0; s < 8; ++s) {
                u32 a[4];
                ldsm4(a, a_lane + (u32)s * 32u);
                u32 b0 = *(const u32*)&hW16[qr * HW_P + 16 * s + qc * 2];
                u32 b1 = *(const u32*)&hW16[qr * HW_P + 16 * s + 8 + qc * 2];
                mma4(cH, a, b0, b1);
            }
            int row0 = (wt << 4) + qr, row1 = row0 + 8;
            float t00 = 0.01f + 2.99f * sigmoid_exact(cH[0]);
            float t01 = 0.01f + 2.99f * sigmoid_exact(cH[1]);
            float t10 = 0.01f + 2.99f * sigmoid_exact(cH[2]);
            float t11 = 0.01f + 2.99f * sigmoid_exact(cH[3]);
            th_s[row0 * 8 + qc * 2]     = t00;
            th_s[row0 * 8 + qc * 2 + 1] = t01;
            th_s[row1 * 8 + qc * 2]     = t10;
            th_s[row1 * 8 + qc * 2 + 1] = t11;
            size_t ob0 = (((size_t)(R0 + row0)) * K_STEPS + k) * 8 + qc * 2;
            size_t ob1 = (((size_t)(R0 + row1)) * K_STEPS + k) * 8 + qc * 2;
            theta_out[ob0] = t00; theta_out[ob0 + 1] = t01;
            theta_out[ob1] = t10; theta_out[ob1 + 1] = t11;
            __syncwarp();

            // RK4(k): all 32 lanes (row = trow; upper half redundant, feeds lift)
            #pragma unroll
            for (int p = 0; p < 5; ++p)
                y[p] += uc0 * uj_s[p] + uc1 * uj_s[5 + p] + uc2 * uj_s[10 + p];
            float th[8];
            #pragma unroll
            for (int i = 0; i < 8; ++i) th[i] = th_s[trow * 8 + i];
            float hs = dtc * 0.1f, hh = 0.5f * hs, h6 = hs * (1.f / 6.f);
            for (int s = 0; s < 10; ++s) {
                float k1[5], k2[5], k3[5], k4[5], yt[5];
                rhs5(y, th, k1);
                #pragma unroll
                for (int i = 0; i < 5; ++i) yt[i] = fmaf(hh, k1[i], y[i]);
                rhs5(yt, th, k2);
                #pragma unroll
                for (int i = 0; i < 5; ++i) yt[i] = fmaf(hh, k2[i], y[i]);
                rhs5(yt, th, k3);
                #pragma unroll
                for (int i = 0; i < 5; ++i) yt[i] = fmaf(hs, k3[i], y[i]);
                rhs5(yt, th, k4);
                #pragma unroll
                for (int i = 0; i < 5; ++i) {
                    float incr = k1[i] + 2.f * k2[i] + 2.f * k3[i] + k4[i];
                    y[i] = fmaxf(fmaf(h6, incr, y[i]), 0.f);
                }
            }
            if (lane < 16) {
                #pragma unroll
                for (int i = 0; i < 5; ++i)
                    y_out[(((size_t)(R0 + trow)) * K_STEPS + k) * 5 + i] = y[i];
            }
            // lift(k+1): only the y-dependent part remains
            if (k + 1 < K_STEPS) {
                #pragma unroll
                for (int i = 0; i < 8; ++i) {
                    int l0 = lbase + 2 * i;
                    float a0 = pre[2 * i], a1 = pre[2 * i + 1];
                    #pragma unroll
                    for (int q = 0; q < 5; ++q) {
                        a0 = fmaf(lW_s[l0 * 8 + 3 + q], y[q], a0);
                        a1 = fmaf(lW_s[(l0 + 1) * 8 + 3 + q], y[q], a1);
                    }
                    *(u32*)&x16[trow * X16_P + l0] =
                        packh2(a0 * sig_fast(a0), a1 * sig_fast(a1));
                }
                uc0 = un0; uc1 = un1; uc2 = un2; dtc = dtn;
            }
        }
        __syncthreads();                    // B: x(k+1) ready; gh reads done

        // phase 3
        if (is_mma && k + 1 < K_STEPS) do_gi();
    }
}

extern "C" void kernel_launch(void* const* d_in, const int* in_sizes, int n_in,
                              void* d_out, int out_size) {
    const float* y0     = (const float*)d_in[0];
    const float* u_seq  = (const float*)d_in[1];
    const float* dt_seq = (const float*)d_in[2];
    const float* lift_W = (const float*)d_in[3];
    const float* lift_b = (const float*)d_in[4];
    const float* W_ih   = (const float*)d_in[5];
    const float* W_hh   = (const float*)d_in[6];
    const float* b_ih   = (const float*)d_in[7];
    const float* b_hh   = (const float*)d_in[8];
    const float* head_W = (const float*)d_in[9];
    const float* head_b = (const float*)d_in[10];
    const float* ujump  = (const float*)d_in[11];

    float* y_out     = (float*)d_out;
    float* theta_out = y_out + (size_t)B_TOT * K_STEPS * 5;

    cudaFuncSetAttribute(rnn_main, cudaFuncAttributeMaxDynamicSharedMemorySize,
                         SMEM_TOTAL);
    rnn_main<<<B_TOT / M_ROWS, THREADS, SMEM_TOTAL>>>(
        y0, u_seq, dt_seq, lift_W, lift_b, W_ih, W_hh, b_ih, b_hh,
        head_W, head_b, ujump, y_out, theta_out);
}

// round 13
// speedup vs baseline: 1.1082x; 1.1082x over previous
#include <cuda_runtime.h>
#include <cuda_fp16.h>
#include <cstdint>

typedef unsigned int u32;

#define B_TOT   4096
#define K_STEPS 512
#define M_ROWS  32
#define THREADS 320

#define H16_P 136
#define X16_P 40
#define HW_P  136
#define WIH_P 40
#define WHN_P 136
#define H32_P 132

// dynamic smem byte offsets
#define HB0_OFF   0         // 32*136*2 = 8704
#define HB1_OFF   8704      // 8704
#define X16_OFF   17408     // 32*40*2 = 2560
#define WIH_OFF   19968     // 3*128*40*2 = 30720
#define WHN_OFF   50688     // 128*136*2 = 34816  (W_hh n-gate)
#define HW_OFF    85504     // 8*136*2 = 2176
#define H32_OFF   87680     // 32*132*4 = 16896   (h fp32 master)
#define BIAS_OFF  104576    // 128*4*4 = 2048     (bR,bZ,bNI,bNH per j)
#define F32_OFF   106624    // misc floats
#define SMEM_TOTAL 109056

__device__ __forceinline__ u32 packh2(float a, float b) {
    __half2 h = __floats2half2_rn(a, b);
    return *(u32*)&h;
}
__device__ __forceinline__ float tanh_fast(float x) {
    float r; asm("tanh.approx.f32 %0,%1;" : "=f"(r) : "f"(x)); return r;
}
__device__ __forceinline__ float sig_fast(float x) {
    return fmaf(tanh_fast(0.5f * x), 0.5f, 0.5f);
}
__device__ __forceinline__ float sigmoid_exact(float x) {
    x = fminf(fmaxf(x, -30.f), 30.f);
    return __fdividef(1.f, 1.f + __expf(-x));
}
__device__ __forceinline__ void rhs5(const float* y, const float* th, float* d) {
    float f1 = th[0] * y[0] - th[4] * y[1];
    float f2 = th[1] * y[1] - th[5] * y[2];
    float f3 = th[2] * y[2] - th[6] * y[3];
    float f4 = th[3] * y[3] - th[7] * y[4];
    d[0] = -f1; d[1] = f1 - f2; d[2] = f2 - f3; d[3] = f3 - f4; d[4] = f4;
}
__device__ __forceinline__ void mma4(float* c, const u32* a, u32 b0, u32 b1) {
    asm volatile(
        "mma.sync.aligned.m16n8k16.row.col.f32.f16.f16.f32 "
        "{%0,%1,%2,%3},{%4,%5,%6,%7},{%8,%9},{%0,%1,%2,%3};"
        : "+f"(c[0]), "+f"(c[1]), "+f"(c[2]), "+f"(c[3])
        : "r"(a[0]), "r"(a[1]), "r"(a[2]), "r"(a[3]), "r"(b0), "r"(b1));
}
__device__ __forceinline__ void ldsm4(u32* a, u32 sa) {
    asm volatile("ldmatrix.sync.aligned.m8n8.x4.shared.b16 {%0,%1,%2,%3},[%4];"
        : "=r"(a[0]), "=r"(a[1]), "=r"(a[2]), "=r"(a[3]) : "r"(sa));
}

__global__ void __launch_bounds__(THREADS, 1)
rnn_main(const float* __restrict__ y0,
         const float* __restrict__ u_seq,
         const float* __restrict__ dt_seq,
         const float* __restrict__ lift_W,
         const float* __restrict__ lift_b,
         const float* __restrict__ W_ih,
         const float* __restrict__ W_hh,
         const float* __restrict__ b_ih,
         const float* __restrict__ b_hh,
         const float* __restrict__ head_W,
         const float* __restrict__ head_b,
         const float* __restrict__ ujump,
         float* __restrict__ y_out,
         float* __restrict__ theta_out) {
    extern __shared__ char smc[];
    __half* hbuf0 = (__half*)(smc + HB0_OFF);
    __half* hbuf1 = (__half*)(smc + HB1_OFF);
    __half* x16   = (__half*)(smc + X16_OFF);
    __half* wih16 = (__half*)(smc + WIH_OFF);
    __half* whn16 = (__half*)(smc + WHN_OFF);
    __half* hW16  = (__half*)(smc + HW_OFF);
    float*  h32   = (float*)(smc + H32_OFF);
    float*  bias4 = (float*)(smc + BIAS_OFF);
    float*  fm    = (float*)(smc + F32_OFF);
    float* lW_s = fm;          // 256
    float* lb_s = fm + 256;    // 32
    float* hb_s = fm + 288;    // 8
    float* uj_s = fm + 296;    // 16
    float* th_s = fm + 312;    // 256

    const int t = threadIdx.x, w = t >> 5, lane = t & 31;
    const int qr = lane >> 2, qc = lane & 3;
    const int R0 = blockIdx.x * M_ROWS;
    const int lm = lane >> 3;
    const bool is_mma = (w < 8);

    // ---------------- prologue: smem staging (all warps) ----------------
    for (int i = t; i < 32 * H16_P / 2; i += THREADS) {
        ((u32*)hbuf0)[i] = 0;
        ((u32*)hbuf1)[i] = 0;
    }
    for (int i = t; i < 32 * H32_P; i += THREADS) h32[i] = 0.f;
    for (int i = t; i < 3 * 128 * 32; i += THREADS) {
        int g = i >> 12, rem = i & 4095, jj = rem >> 5, l = rem & 31;
        wih16[g * 128 * WIH_P + jj * WIH_P + l] = __float2half_rn(W_ih[i]);
    }
    for (int i = t; i < 128 * 128; i += THREADS) {
        int jj = i >> 7, kk = i & 127;
        whn16[jj * WHN_P + kk] = __float2half_rn(W_hh[(256 + jj) * 128 + kk]);
    }
    for (int i = t; i < 1024; i += THREADS) {
        int c = i >> 7, kk = i & 127;
        hW16[c * HW_P + kk] = __float2half_rn(head_W[i]);
    }
    for (int i = t; i < 128; i += THREADS) {
        bias4[i * 4 + 0] = b_ih[i] + b_hh[i];
        bias4[i * 4 + 1] = b_ih[128 + i] + b_hh[128 + i];
        bias4[i * 4 + 2] = b_ih[256 + i];
        bias4[i * 4 + 3] = b_hh[256 + i];
    }
    for (int i = t; i < 256; i += THREADS) lW_s[i] = lift_W[i];
    if (t < 32) lb_s[t] = lift_b[t];
    if (t < 8)  hb_s[t] = head_b[t];
    if (t < 15) uj_s[t] = ujump[t];

    u32 smb;
    asm("{ .reg .u64 tt; cvta.to.shared.u64 tt, %1; cvt.u32.u64 %0, tt; }"
        : "=r"(smb) : "l"((const void*)smc));

    // ---------------- MMA-warp constants ----------------
    const int wj = (w & 7) * 16;
    const int j_lo = wj + qr, j_hi = j_lo + 8;
    u32 agh[2][8][4];     // r,z gate W_hh frags in regs; n-gate via ldsm
    if (is_mma) {
        #pragma unroll
        for (int g = 0; g < 2; ++g)
            #pragma unroll
            for (int s = 0; s < 8; ++s) {
                const float* p = W_hh + (g * 128 + j_lo) * 128 + 16 * s + qc * 2;
                agh[g][s][0] = packh2(p[0], p[1]);
                agh[g][s][1] = packh2(p[1024], p[1025]);
                agh[g][s][2] = packh2(p[8], p[9]);
                agh[g][s][3] = packh2(p[1032], p[1033]);
            }
    }
    const u32 wih_lane = smb + WIH_OFF +
        (u32)((wj + (lm & 1) * 8 + (lane & 7)) * WIH_P + (lm >> 1) * 8) * 2u;
    const u32 whn_lane = smb + WHN_OFF +
        (u32)((wj + (lm & 1) * 8 + (lane & 7)) * WHN_P + (lm >> 1) * 8) * 2u;

    // ---------------- tail-warp state (w8/w9) ----------------
    const int wt = w - 8;
    const int trow = (wt << 4) + (lane & 15);
    const u32 head_row_off =
        (u32)(((wt << 4) + (lm & 1) * 8 + (lane & 7)) * H16_P + (lm >> 1) * 8) * 2u;
    const int lbase = lane & 16;
    float y[5] = {0, 0, 0, 0, 0};
    float pre[16];
    float uc0 = 0, uc1 = 0, uc2 = 0, dtc = 0;
    float un0 = 0, un1 = 0, un2 = 0, dtn = 0;
    if (!is_mma) {
        #pragma unroll
        for (int i = 0; i < 5; ++i) y[i] = y0[(R0 + trow) * 5 + i] + 0.01f;
        const float* up = u_seq + ((size_t)(R0 + trow) * K_STEPS) * 3;
        uc0 = up[0]; uc1 = up[1]; uc2 = up[2];
        dtc = dt_seq[(size_t)(R0 + trow) * K_STEPS];
    }

    float cR[4][4], cZ[4][4], cNI[4][4], cNH[4][4];

    auto init_accs = [&]() {
        const float4 blo = *(const float4*)(bias4 + j_lo * 4);
        const float4 bhi = *(const float4*)(bias4 + j_hi * 4);
        #pragma unroll
        for (int nt = 0; nt < 4; ++nt) {
            cR[nt][0] = blo.x;  cR[nt][1] = blo.x;  cR[nt][2] = bhi.x;  cR[nt][3] = bhi.x;
            cZ[nt][0] = blo.y;  cZ[nt][1] = blo.y;  cZ[nt][2] = bhi.y;  cZ[nt][3] = bhi.y;
            cNI[nt][0] = blo.z; cNI[nt][1] = blo.z; cNI[nt][2] = bhi.z; cNI[nt][3] = bhi.z;
            cNH[nt][0] = blo.w; cNH[nt][1] = blo.w; cNH[nt][2] = bhi.w; cNH[nt][3] = bhi.w;
        }
    };
    auto do_gh = [&](const __half* hb) {
        #pragma unroll
        for (int s = 0; s < 8; ++s) {
            u32 aN[4];
            ldsm4(aN, whn_lane + (u32)s * 32u);
            #pragma unroll
            for (int nt = 0; nt < 4; ++nt) {
                const __half* hp = hb + (qr + 8 * nt) * H16_P + 16 * s + qc * 2;
                u32 b0 = *(const u32*)hp;
                u32 b1 = *(const u32*)(hp + 8);
                mma4(cR[nt],  agh[0][s], b0, b1);
                mma4(cZ[nt],  agh[1][s], b0, b1);
                mma4(cNH[nt], aN, b0, b1);
            }
        }
    };
    auto do_gi = [&]() {
        #pragma unroll
        for (int s = 0; s < 2; ++s) {
            u32 aR_[4], aZ_[4], aN_[4];
            ldsm4(aR_, wih_lane + (u32)s * 32u);
            ldsm4(aZ_, wih_lane + 10240u + (u32)s * 32u);
            ldsm4(aN_, wih_lane + 20480u + (u32)s * 32u);
            #pragma unroll
            for (int nt = 0; nt < 4; ++nt) {
                const __half* xp = x16 + (qr + 8 * nt) * X16_P + 16 * s + qc * 2;
                u32 b0 = *(const u32*)xp;
                u32 b1 = *(const u32*)(xp + 8);
                mma4(cR[nt],  aR_, b0, b1);
                mma4(cZ[nt],  aZ_, b0, b1);
                mma4(cNI[nt], aN_, b0, b1);
            }
        }
    };
    auto epilogue = [&](__half* hb) {
        #pragma unroll
        for (int nt = 0; nt < 4; ++nt) {
            int r0 = qc * 2 + 8 * nt;
            float hn[4];
            float ho0 = h32[r0 * H32_P + j_lo];
            float ho1 = h32[(r0 + 1) * H32_P + j_lo];
            float ho2 = h32[r0 * H32_P + j_hi];
            float ho3 = h32[(r0 + 1) * H32_P + j_hi];
            float ho[4] = {ho0, ho1, ho2, ho3};
            #pragma unroll
            for (int c = 0; c < 4; ++c) {
                float gr = sig_fast(cR[nt][c]);
                float gz = sig_fast(cZ[nt][c]);
                float gn = tanh_fast(fmaf(gr, cNH[nt][c], cNI[nt][c]));
                hn[c] = (1.f - gz) * gn + gz * ho[c];
            }
            h32[r0 * H32_P + j_lo]       = hn[0];
            h32[(r0 + 1) * H32_P + j_lo] = hn[1];
            h32[r0 * H32_P + j_hi]       = hn[2];
            h32[(r0 + 1) * H32_P + j_hi] = hn[3];
            hb[r0 * H16_P + j_lo]       = __float2half_rn(hn[0]);
            hb[(r0 + 1) * H16_P + j_lo] = __float2half_rn(hn[1]);
            hb[r0 * H16_P + j_hi]       = __float2half_rn(hn[2]);
            hb[(r0 + 1) * H16_P + j_hi] = __float2half_rn(hn[3]);
        }
    };

    __syncthreads();
    // pre-loop: tail computes x(0); then MMA warps build gates(0) (gh(0)=0)
    if (!is_mma) {
        float f[8];
        f[0] = uc0; f[1] = uc1; f[2] = uc2;
        #pragma unroll
        for (int i = 0; i < 5; ++i) f[3 + i] = y[i];
        #pragma unroll
        for (int i = 0; i < 8; ++i) {
            int l0 = lbase + 2 * i;
            float a0 = lb_s[l0], a1 = lb_s[l0 + 1];
            #pragma unroll
            for (int q = 0; q < 8; ++q) {
                a0 = fmaf(lW_s[l0 * 8 + q], f[q], a0);
                a1 = fmaf(lW_s[(l0 + 1) * 8 + q], f[q], a1);
            }
            *(u32*)&x16[trow * X16_P + l0] =
                packh2(a0 * sig_fast(a0), a1 * sig_fast(a1));
        }
    }
    __syncthreads();
    if (is_mma) { init_accs(); do_gi(); }

    // ---------------- main loop: 2 barriers/step ----------------
    for (int k = 0; k < K_STEPS; ++k) {
        __half* hb_cur = (k & 1) ? hbuf1 : hbuf0;
        // phase 1
        if (is_mma) {
            epilogue(hb_cur);               // h(k)
        } else if (k + 1 < K_STEPS) {
            const float* up = u_seq + ((size_t)(R0 + trow) * K_STEPS + (k + 1)) * 3;
            un0 = up[0]; un1 = up[1]; un2 = up[2];
            dtn = dt_seq[(size_t)(R0 + trow) * K_STEPS + (k + 1)];
            #pragma unroll
            for (int i = 0; i < 16; ++i) {
                int l = lbase + i;
                float a = lb_s[l];
                a = fmaf(lW_s[l * 8 + 0], un0, a);
                a = fmaf(lW_s[l * 8 + 1], un1, a);
                a = fmaf(lW_s[l * 8 + 2], un2, a);
                pre[i] = a;
            }
        }
        __syncthreads();                    // A: h(k) visible

        // phase 2
        if (is_mma) {
            if (k + 1 < K_STEPS) { init_accs(); do_gh(hb_cur); }
        } else {
            // head(k): one 16-row tile per tail warp
            float cH[4];
            cH[0] = hb_s[qc * 2]; cH[1] = hb_s[qc * 2 + 1];
            cH[2] = cH[0];        cH[3] = cH[1];
            u32 a_lane = smb + ((k & 1) ? HB1_OFF : HB0_OFF) + head_row_off;
            #pragma unroll
            for (int s = 0; s < 8; ++s) {
                u32 a[4];
                ldsm4(a, a_lane + (u32)s * 32u);
                u32 b0 = *(const u32*)&hW16[qr * HW_P + 16 * s + qc * 2];
                u32 b1 = *(const u32*)&hW16[qr * HW_P + 16 * s + 8 + qc * 2];
                mma4(cH, a, b0, b1);
            }
            int row0 = (wt << 4) + qr, row1 = row0 + 8;
            float t00 = 0.01f + 2.99f * sigmoid_exact(cH[0]);
            float t01 = 0.01f + 2.99f * sigmoid_exact(cH[1]);
            float t10 = 0.01f + 2.99f * sigmoid_exact(cH[2]);
            float t11 = 0.01f + 2.99f * sigmoid_exact(cH[3]);
            th_s[row0 * 8 + qc * 2]     = t00;
            th_s[row0 * 8 + qc * 2 + 1] = t01;
            th_s[row1 * 8 + qc * 2]     = t10;
            th_s[row1 * 8 + qc * 2 + 1] = t11;
            size_t ob0 = (((size_t)(R0 + row0)) * K_STEPS + k) * 8 + qc * 2;
            size_t ob1 = (((size_t)(R0 + row1)) * K_STEPS + k) * 8 + qc * 2;
            theta_out[ob0] = t00; theta_out[ob0 + 1] = t01;
            theta_out[ob1] = t10; theta_out[ob1 + 1] = t11;
            __syncwarp();

            // RK4(k): 32 lanes, row = trow (upper half redundant, feeds lift)
            #pragma unroll
            for (int p = 0; p < 5; ++p)
                y[p] += uc0 * uj_s[p] + uc1 * uj_s[5 + p] + uc2 * uj_s[10 + p];
            float th[8];
            #pragma unroll
            for (int i = 0; i < 8; ++i) th[i] = th_s[trow * 8 + i];
            float hs = dtc * 0.1f, hh = 0.5f * hs, h6 = hs * (1.f / 6.f);
            for (int s = 0; s < 10; ++s) {
                float k1[5], k2[5], k3[5], k4[5], yt[5];
                rhs5(y, th, k1);
                #pragma unroll
                for (int i = 0; i < 5; ++i) yt[i] = fmaf(hh, k1[i], y[i]);
                rhs5(yt, th, k2);
                #pragma unroll
                for (int i = 0; i < 5; ++i) yt[i] = fmaf(hh, k2[i], y[i]);
                rhs5(yt, th, k3);
                #pragma unroll
                for (int i = 0; i < 5; ++i) yt[i] = fmaf(hs, k3[i], y[i]);
                rhs5(yt, th, k4);
                #pragma unroll
                for (int i = 0; i < 5; ++i) {
                    float incr = k1[i] + 2.f * k2[i] + 2.f * k3[i] + k4[i];
                    y[i] = fmaxf(fmaf(h6, incr, y[i]), 0.f);
                }
            }
            if (lane < 16) {
                #pragma unroll
                for (int i = 0; i < 5; ++i)
                    y_out[(((size_t)(R0 + trow)) * K_STEPS + k) * 5 + i] = y[i];
            }
            // lift(k+1): y-dependent part only
            if (k + 1 < K_STEPS) {
                #pragma unroll
                for (int i = 0; i < 8; ++i) {
                    int l0 = lbase + 2 * i;
                    float a0 = pre[2 * i], a1 = pre[2 * i + 1];
                    #pragma unroll
                    for (int q = 0; q < 5; ++q) {
                        a0 = fmaf(lW_s[l0 * 8 + 3 + q], y[q], a0);
                        a1 = fmaf(lW_s[(l0 + 1) * 8 + 3 + q], y[q], a1);
                    }
                    *(u32*)&x16[trow * X16_P + l0] =
                        packh2(a0 * sig_fast(a0), a1 * sig_fast(a1));
                }
                uc0 = un0; uc1 = un1; uc2 = un2; dtc = dtn;
            }
        }
        __syncthreads();                    // B: x(k+1) ready; gh reads done

        // phase 3
        if (is_mma && k + 1 < K_STEPS) do_gi();
    }
}

extern "C" void kernel_launch(void* const* d_in, const int* in_sizes, int n_in,
                              void* d_out, int out_size) {
    const float* y0     = (const float*)d_in[0];
    const float* u_seq  = (const float*)d_in[1];
    const float* dt_seq = (const float*)d_in[2];
    const float* lift_W = (const float*)d_in[3];
    const float* lift_b = (const float*)d_in[4];
    const float* W_ih   = (const float*)d_in[5];
    const float* W_hh   = (const float*)d_in[6];
    const float* b_ih   = (const float*)d_in[7];
    const float* b_hh   = (const float*)d_in[8];
    const float* head_W = (const float*)d_in[9];
    const float* head_b = (const float*)d_in[10];
    const float* ujump  = (const float*)d_in[11];

    float* y_out     = (float*)d_out;
    float* theta_out = y_out + (size_t)B_TOT * K_STEPS * 5;

    cudaFuncSetAttribute(rnn_main, cudaFuncAttributeMaxDynamicSharedMemorySize,
                         SMEM_TOTAL);
    rnn_main<<<B_TOT / M_ROWS, THREADS, SMEM_TOTAL>>>(
        y0, u_seq, dt_seq, lift_W, lift_b, W_ih, W_hh, b_ih, b_hh,
        head_W, head_b, ujump, y_out, theta_out);
}

// round 14
// speedup vs baseline: 1.2700x; 1.1460x over previous
#include <cuda_runtime.h>
#include <cuda_fp16.h>
#include <cstdint>

typedef unsigned int u32;

#define B_TOT   4096
#define K_STEPS 512
#define M_ROWS  32
#define THREADS 320

#define H16_P 136
#define X16_P 40
#define HW_P  136
#define WIH_P 40
#define WHN_P 136
#define H32_P 132

// dynamic smem byte offsets
#define HB0_OFF   0         // 32*136*2 = 8704
#define HB1_OFF   8704
#define X16_OFF   17408     // 32*40*2 = 2560
#define WIH_OFF   19968     // 3*128*40*2 = 30720
#define WHN_OFF   50688     // 128*136*2 = 34816  (W_hh n-gate)
#define HW_OFF    85504     // 8*136*2 = 2176
#define H32_OFF   87680     // 32*132*4 = 16896   (h fp32 master)
#define BIAS_OFF  104576    // 128*4*4 = 2048
#define F32_OFF   106624
#define SMEM_TOTAL 109056

#define BAR_SYNC(id, cnt)   asm volatile("bar.sync %0, %1;"   :: "r"(id), "r"(cnt) : "memory")
#define BAR_ARRIVE(id, cnt) asm volatile("bar.arrive %0, %1;" :: "r"(id), "r"(cnt) : "memory")

__device__ __forceinline__ u32 packh2(float a, float b) {
    __half2 h = __floats2half2_rn(a, b);
    return *(u32*)&h;
}
__device__ __forceinline__ float tanh_fast(float x) {
    float r; asm("tanh.approx.f32 %0,%1;" : "=f"(r) : "f"(x)); return r;
}
__device__ __forceinline__ float sig_fast(float x) {
    return fmaf(tanh_fast(0.5f * x), 0.5f, 0.5f);
}
__device__ __forceinline__ void rhs5(const float* y, const float* th, float* d) {
    float f1 = th[0] * y[0] - th[4] * y[1];
    float f2 = th[1] * y[1] - th[5] * y[2];
    float f3 = th[2] * y[2] - th[6] * y[3];
    float f4 = th[3] * y[3] - th[7] * y[4];
    d[0] = -f1; d[1] = f1 - f2; d[2] = f2 - f3; d[3] = f3 - f4; d[4] = f4;
}
__device__ __forceinline__ void mma4(float* c, const u32* a, u32 b0, u32 b1) {
    asm volatile(
        "mma.sync.aligned.m16n8k16.row.col.f32.f16.f16.f32 "
        "{%0,%1,%2,%3},{%4,%5,%6,%7},{%8,%9},{%0,%1,%2,%3};"
        : "+f"(c[0]), "+f"(c[1]), "+f"(c[2]), "+f"(c[3])
        : "r"(a[0]), "r"(a[1]), "r"(a[2]), "r"(a[3]), "r"(b0), "r"(b1));
}
__device__ __forceinline__ void ldsm4(u32* a, u32 sa) {
    asm volatile("ldmatrix.sync.aligned.m8n8.x4.shared.b16 {%0,%1,%2,%3},[%4];"
        : "=r"(a[0]), "=r"(a[1]), "=r"(a[2]), "=r"(a[3]) : "r"(sa));
}

__global__ void __launch_bounds__(THREADS, 1)
rnn_main(const float* __restrict__ y0,
         const float* __restrict__ u_seq,
         const float* __restrict__ dt_seq,
         const float* __restrict__ lift_W,
         const float* __restrict__ lift_b,
         const float* __restrict__ W_ih,
         const float* __restrict__ W_hh,
         const float* __restrict__ b_ih,
         const float* __restrict__ b_hh,
         const float* __restrict__ head_W,
         const float* __restrict__ head_b,
         const float* __restrict__ ujump,
         float* __restrict__ y_out,
         float* __restrict__ theta_out) {
    extern __shared__ char smc[];
    __half* hbuf0 = (__half*)(smc + HB0_OFF);
    __half* hbuf1 = (__half*)(smc + HB1_OFF);
    __half* x16   = (__half*)(smc + X16_OFF);
    __half* wih16 = (__half*)(smc + WIH_OFF);
    __half* whn16 = (__half*)(smc + WHN_OFF);
    __half* hW16  = (__half*)(smc + HW_OFF);
    float*  h32   = (float*)(smc + H32_OFF);
    float*  bias4 = (float*)(smc + BIAS_OFF);
    float*  fm    = (float*)(smc + F32_OFF);
    float* lW_s = fm;          // 256
    float* lb_s = fm + 256;    // 32
    float* hb_s = fm + 288;    // 8
    float* uj_s = fm + 296;    // 16
    float* th_s = fm + 312;    // 256

    const int t = threadIdx.x, w = t >> 5, lane = t & 31;
    const int qr = lane >> 2, qc = lane & 3;
    const int R0 = blockIdx.x * M_ROWS;
    const int lm = lane >> 3;
    const bool is_mma = (w < 8);

    // ---------------- prologue: smem staging (all warps) ----------------
    for (int i = t; i < 32 * H16_P / 2; i += THREADS) {
        ((u32*)hbuf0)[i] = 0;
        ((u32*)hbuf1)[i] = 0;
    }
    for (int i = t; i < 32 * H32_P; i += THREADS) h32[i] = 0.f;
    for (int i = t; i < 3 * 128 * 32; i += THREADS) {
        int g = i >> 12, rem = i & 4095, jj = rem >> 5, l = rem & 31;
        wih16[g * 128 * WIH_P + jj * WIH_P + l] = __float2half_rn(W_ih[i]);
    }
    for (int i = t; i < 128 * 128; i += THREADS) {
        int jj = i >> 7, kk = i & 127;
        whn16[jj * WHN_P + kk] = __float2half_rn(W_hh[(256 + jj) * 128 + kk]);
    }
    for (int i = t; i < 1024; i += THREADS) {
        int c = i >> 7, kk = i & 127;
        hW16[c * HW_P + kk] = __float2half_rn(head_W[i]);
    }
    for (int i = t; i < 128; i += THREADS) {
        bias4[i * 4 + 0] = b_ih[i] + b_hh[i];
        bias4[i * 4 + 1] = b_ih[128 + i] + b_hh[128 + i];
        bias4[i * 4 + 2] = b_ih[256 + i];
        bias4[i * 4 + 3] = b_hh[256 + i];
    }
    for (int i = t; i < 256; i += THREADS) lW_s[i] = lift_W[i];
    if (t < 32) lb_s[t] = lift_b[t];
    if (t < 8)  hb_s[t] = head_b[t];
    if (t < 15) uj_s[t] = ujump[t];

    u32 smb;
    asm("{ .reg .u64 tt; cvta.to.shared.u64 tt, %1; cvt.u32.u64 %0, tt; }"
        : "=r"(smb) : "l"((const void*)smc));

    // ---------------- MMA-warp constants ----------------
    const int wj = (w & 7) * 16;
    const int j_lo = wj + qr, j_hi = j_lo + 8;
    u32 agh[2][8][4];     // r,z gate W_hh frags in regs; n-gate via ldsm
    if (is_mma) {
        #pragma unroll
        for (int g = 0; g < 2; ++g)
            #pragma unroll
            for (int s = 0; s < 8; ++s) {
                const float* p = W_hh + (g * 128 + j_lo) * 128 + 16 * s + qc * 2;
                agh[g][s][0] = packh2(p[0], p[1]);
                agh[g][s][1] = packh2(p[1024], p[1025]);
                agh[g][s][2] = packh2(p[8], p[9]);
                agh[g][s][3] = packh2(p[1032], p[1033]);
            }
    }
    const u32 wih_lane = smb + WIH_OFF +
        (u32)((wj + (lm & 1) * 8 + (lane & 7)) * WIH_P + (lm >> 1) * 8) * 2u;
    const u32 whn_lane = smb + WHN_OFF +
        (u32)((wj + (lm & 1) * 8 + (lane & 7)) * WHN_P + (lm >> 1) * 8) * 2u;

    // ---------------- tail-warp state (w8/w9) ----------------
    const int wt = w - 8;
    const int trow = (wt << 4) + (lane & 15);
    const u32 head_row_off =
        (u32)(((wt << 4) + (lm & 1) * 8 + (lane & 7)) * H16_P + (lm >> 1) * 8) * 2u;
    const int lbase = lane & 16;
    float y[5] = {0, 0, 0, 0, 0};
    float pre[16];
    float uc0 = 0, uc1 = 0, uc2 = 0, dtc = 0;
    if (!is_mma) {
        #pragma unroll
        for (int i = 0; i < 5; ++i) y[i] = y0[(R0 + trow) * 5 + i] + 0.01f;
        const float* up = u_seq + ((size_t)(R0 + trow) * K_STEPS) * 3;
        uc0 = up[0]; uc1 = up[1]; uc2 = up[2];
        dtc = dt_seq[(size_t)(R0 + trow) * K_STEPS];
    }

    float cR[4][4], cZ[4][4], cNI[4][4], cNH[4][4];

    auto init_accs = [&]() {
        const float4 blo = *(const float4*)(bias4 + j_lo * 4);
        const float4 bhi = *(const float4*)(bias4 + j_hi * 4);
        #pragma unroll
        for (int nt = 0; nt < 4; ++nt) {
            cR[nt][0] = blo.x;  cR[nt][1] = blo.x;  cR[nt][2] = bhi.x;  cR[nt][3] = bhi.x;
            cZ[nt][0] = blo.y;  cZ[nt][1] = blo.y;  cZ[nt][2] = bhi.y;  cZ[nt][3] = bhi.y;
            cNI[nt][0] = blo.z; cNI[nt][1] = blo.z; cNI[nt][2] = bhi.z; cNI[nt][3] = bhi.z;
            cNH[nt][0] = blo.w; cNH[nt][1] = blo.w; cNH[nt][2] = bhi.w; cNH[nt][3] = bhi.w;
        }
    };
    auto do_gh = [&](const __half* hb) {
        #pragma unroll
        for (int s = 0; s < 8; ++s) {
            u32 aN[4];
            ldsm4(aN, whn_lane + (u32)s * 32u);
            #pragma unroll
            for (int nt = 0; nt < 4; ++nt) {
                const __half* hp = hb + (qr + 8 * nt) * H16_P + 16 * s + qc * 2;
                u32 b0 = *(const u32*)hp;
                u32 b1 = *(const u32*)(hp + 8);
                mma4(cR[nt],  agh[0][s], b0, b1);
                mma4(cZ[nt],  agh[1][s], b0, b1);
                mma4(cNH[nt], aN, b0, b1);
            }
        }
    };
    auto do_gi = [&]() {
        #pragma unroll
        for (int s = 0; s < 2; ++s) {
            u32 aR_[4], aZ_[4], aN_[4];
            ldsm4(aR_, wih_lane + (u32)s * 32u);
            ldsm4(aZ_, wih_lane + 10240u + (u32)s * 32u);
            ldsm4(aN_, wih_lane + 20480u + (u32)s * 32u);
            #pragma unroll
            for (int nt = 0; nt < 4; ++nt) {
                const __half* xp = x16 + (qr + 8 * nt) * X16_P + 16 * s + qc * 2;
                u32 b0 = *(const u32*)xp;
                u32 b1 = *(const u32*)(xp + 8);
                mma4(cR[nt],  aR_, b0, b1);
                mma4(cZ[nt],  aZ_, b0, b1);
                mma4(cNI[nt], aN_, b0, b1);
            }
        }
    };
    auto epilogue = [&](__half* hb) {
        #pragma unroll
        for (int nt = 0; nt < 4; ++nt) {
            int r0 = qc * 2 + 8 * nt;
            float hn[4];
            float ho[4];
            ho[0] = h32[r0 * H32_P + j_lo];
            ho[1] = h32[(r0 + 1) * H32_P + j_lo];
            ho[2] = h32[r0 * H32_P + j_hi];
            ho[3] = h32[(r0 + 1) * H32_P + j_hi];
            #pragma unroll
            for (int c = 0; c < 4; ++c) {
                float gr = sig_fast(cR[nt][c]);
                float gz = sig_fast(cZ[nt][c]);
                float gn = tanh_fast(fmaf(gr, cNH[nt][c], cNI[nt][c]));
                hn[c] = (1.f - gz) * gn + gz * ho[c];
            }
            h32[r0 * H32_P + j_lo]       = hn[0];
            h32[(r0 + 1) * H32_P + j_lo] = hn[1];
            h32[r0 * H32_P + j_hi]       = hn[2];
            h32[(r0 + 1) * H32_P + j_hi] = hn[3];
            hb[r0 * H16_P + j_lo]       = __float2half_rn(hn[0]);
            hb[(r0 + 1) * H16_P + j_lo] = __float2half_rn(hn[1]);
            hb[r0 * H16_P + j_hi]       = __float2half_rn(hn[2]);
            hb[(r0 + 1) * H16_P + j_hi] = __float2half_rn(hn[3]);
        }
    };

    __syncthreads();
    // pre-loop: tail computes x(0); then gates(0) accumulators (gh(0)=0)
    if (!is_mma) {
        float f[8];
        f[0] = uc0; f[1] = uc1; f[2] = uc2;
        #pragma unroll
        for (int i = 0; i < 5; ++i) f[3 + i] = y[i];
        #pragma unroll
        for (int i = 0; i < 8; ++i) {
            int l0 = lbase + 2 * i;
            float a0 = lb_s[l0], a1 = lb_s[l0 + 1];
            #pragma unroll
            for (int q = 0; q < 8; ++q) {
                a0 = fmaf(lW_s[l0 * 8 + q], f[q], a0);
                a1 = fmaf(lW_s[(l0 + 1) * 8 + q], f[q], a1);
            }
            *(u32*)&x16[trow * X16_P + l0] =
                packh2(a0 * sig_fast(a0), a1 * sig_fast(a1));
        }
    }
    __syncthreads();
    if (is_mma) { init_accs(); do_gi(); }

    // ---------------- main loop: producer/consumer named barriers ----------
    // B1 (id1,320): h(k) ready   — MMA arrive, tail sync
    // B3 (id3,256): epi done     — MMA-internal sync before gh
    // B2 (id2,320): x(k+1) ready — tail arrive, MMA sync before gi
    for (int k = 0; k < K_STEPS; ++k) {
        if (is_mma) {
            __half* hb_cur = (k & 1) ? hbuf1 : hbuf0;
            epilogue(hb_cur);               // h(k)
            BAR_ARRIVE(1, 320);             // tail may start head(k)
            if (k + 1 < K_STEPS) {
                BAR_SYNC(3, 256);           // all MMA epi writes visible
                init_accs();
                do_gh(hb_cur);
                BAR_SYNC(2, 320);           // wait x(k+1)
                do_gi();
            }
        } else {
            // prefetch u/dt(k+1) + u-part of lift (before blocking wait)
            float un0 = 0, un1 = 0, un2 = 0, dtn = 0;
            if (k + 1 < K_STEPS) {
                const float* up = u_seq + ((size_t)(R0 + trow) * K_STEPS + (k + 1)) * 3;
                un0 = up[0]; un1 = up[1]; un2 = up[2];
                dtn = dt_seq[(size_t)(R0 + trow) * K_STEPS + (k + 1)];
                #pragma unroll
                for (int i = 0; i < 16; ++i) {
                    int l = lbase + i;
                    float a = lb_s[l];
                    a = fmaf(lW_s[l * 8 + 0], un0, a);
                    a = fmaf(lW_s[l * 8 + 1], un1, a);
                    a = fmaf(lW_s[l * 8 + 2], un2, a);
                    pre[i] = a;
                }
            }
            BAR_SYNC(1, 320);               // wait h(k)

            // head(k)
            float cH[4];
            cH[0] = hb_s[qc * 2]; cH[1] = hb_s[qc * 2 + 1];
            cH[2] = cH[0];        cH[3] = cH[1];
            u32 a_lane = smb + ((k & 1) ? HB1_OFF : HB0_OFF) + head_row_off;
            #pragma unroll
            for (int s = 0; s < 8; ++s) {
                u32 a[4];
                ldsm4(a, a_lane + (u32)s * 32u);
                u32 b0 = *(const u32*)&hW16[qr * HW_P + 16 * s + qc * 2];
                u32 b1 = *(const u32*)&hW16[qr * HW_P + 16 * s + 8 + qc * 2];
                mma4(cH, a, b0, b1);
            }
            int row0 = (wt << 4) + qr, row1 = row0 + 8;
            float t00 = 0.01f + 2.99f * sig_fast(cH[0]);
            float t01 = 0.01f + 2.99f * sig_fast(cH[1]);
            float t10 = 0.01f + 2.99f * sig_fast(cH[2]);
            float t11 = 0.01f + 2.99f * sig_fast(cH[3]);
            th_s[row0 * 8 + qc * 2]     = t00;
            th_s[row0 * 8 + qc * 2 + 1] = t01;
            th_s[row1 * 8 + qc * 2]     = t10;
            th_s[row1 * 8 + qc * 2 + 1] = t11;
            size_t ob0 = (((size_t)(R0 + row0)) * K_STEPS + k) * 8 + qc * 2;
            size_t ob1 = (((size_t)(R0 + row1)) * K_STEPS + k) * 8 + qc * 2;
            theta_out[ob0] = t00; theta_out[ob0 + 1] = t01;
            theta_out[ob1] = t10; theta_out[ob1 + 1] = t11;
            __syncwarp();

            // RK4(k): 32 lanes, row = trow (upper half redundant, feeds lift)
            #pragma unroll
            for (int p = 0; p < 5; ++p)
                y[p] += uc0 * uj_s[p] + uc1 * uj_s[5 + p] + uc2 * uj_s[10 + p];
            float th[8];
            #pragma unroll
            for (int i = 0; i < 8; ++i) th[i] = th_s[trow * 8 + i];
            float hs = dtc * 0.1f, hh = 0.5f * hs, h6 = hs * (1.f / 6.f);
            for (int s = 0; s < 10; ++s) {
                float k1[5], k2[5], k3[5], k4[5], yt[5];
                rhs5(y, th, k1);
                #pragma unroll
                for (int i = 0; i < 5; ++i) yt[i] = fmaf(hh, k1[i], y[i]);
                rhs5(yt, th, k2);
                #pragma unroll
                for (int i = 0; i < 5; ++i) yt[i] = fmaf(hh, k2[i], y[i]);
                rhs5(yt, th, k3);
                #pragma unroll
                for (int i = 0; i < 5; ++i) yt[i] = fmaf(hs, k3[i], y[i]);
                rhs5(yt, th, k4);
                #pragma unroll
                for (int i = 0; i < 5; ++i) {
                    float incr = k1[i] + 2.f * k2[i] + 2.f * k3[i] + k4[i];
                    y[i] = fmaxf(fmaf(h6, incr, y[i]), 0.f);
                }
            }
            if (lane < 16) {
                #pragma unroll
                for (int i = 0; i < 5; ++i)
                    y_out[(((size_t)(R0 + trow)) * K_STEPS + k) * 5 + i] = y[i];
            }
            // lift(k+1): y-part, then signal x-ready
            if (k + 1 < K_STEPS) {
                #pragma unroll
                for (int i = 0; i < 8; ++i) {
                    int l0 = lbase + 2 * i;
                    float a0 = pre[2 * i], a1 = pre[2 * i + 1];
                    #pragma unroll
                    for (int q = 0; q < 5; ++q) {
                        a0 = fmaf(lW_s[l0 * 8 + 3 + q], y[q], a0);
                        a1 = fmaf(lW_s[(l0 + 1) * 8 + 3 + q], y[q], a1);
                    }
                    *(u32*)&x16[trow * X16_P + l0] =
                        packh2(a0 * sig_fast(a0), a1 * sig_fast(a1));
                }
                BAR_ARRIVE(2, 320);
                uc0 = un0; uc1 = un1; uc2 = un2; dtc = dtn;
            }
        }
    }
}

extern "C" void kernel_launch(void* const* d_in, const int* in_sizes, int n_in,
                              void* d_out, int out_size) {
    const float* y0     = (const float*)d_in[0];
    const float* u_seq  = (const float*)d_in[1];
    const float* dt_seq = (const float*)d_in[2];
    const float* lift_W = (const float*)d_in[3];
    const float* lift_b = (const float*)d_in[4];
    const float* W_ih   = (const float*)d_in[5];
    const float* W_hh   = (const float*)d_in[6];
    const float* b_ih   = (const float*)d_in[7];
    const float* b_hh   = (const float*)d_in[8];
    const float* head_W = (const float*)d_in[9];
    const float* head_b = (const float*)d_in[10];
    const float* ujump  = (const float*)d_in[11];

    float* y_out     = (float*)d_out;
    float* theta_out = y_out + (size_t)B_TOT * K_STEPS * 5;

    cudaFuncSetAttribute(rnn_main, cudaFuncAttributeMaxDynamicSharedMemorySize,
                         SMEM_TOTAL);
    rnn_main<<<B_TOT / M_ROWS, THREADS, SMEM_TOTAL>>>(
        y0, u_seq, dt_seq, lift_W, lift_b, W_ih, W_hh, b_ih, b_hh,
        head_W, head_b, ujump, y_out, theta_out);
}

// round 15
// speedup vs baseline: 1.5646x; 1.2320x over previous
#include <cuda_runtime.h>
#include <cuda_fp16.h>
#include <cstdint>

typedef unsigned int u32;

#define B_TOT   4096
#define K_STEPS 512
#define M_ROWS  32
#define THREADS 256

#define H16_P 136
#define X16_P 40
#define HW_P  136
#define WIH_P 40

// dynamic smem byte offsets
#define HB0_OFF  0        // h buf0: 32*136 fp16 = 8704
#define HB1_OFF  8704     // h buf1
#define X16_OFF  17408    // 32*40 fp16 = 2560
#define WIH_OFF  19968    // 3*128*40 fp16 = 30720
#define HW_OFF   50688    // 8*136 fp16 = 2176
#define F32_OFF  52864    // floats below
#define SMEM_TOTAL 55168

#define BAR_SYNC(id, cnt)   asm volatile("bar.sync %0, %1;"   :: "r"(id), "r"(cnt) : "memory")
#define BAR_ARRIVE(id, cnt) asm volatile("bar.arrive %0, %1;" :: "r"(id), "r"(cnt) : "memory")

__device__ __forceinline__ u32 packh2(float a, float b) {
    __half2 h = __floats2half2_rn(a, b);
    return *(u32*)&h;
}
__device__ __forceinline__ float tanh_fast(float x) {
    float r; asm("tanh.approx.f32 %0,%1;" : "=f"(r) : "f"(x)); return r;
}
__device__ __forceinline__ float sig_fast(float x) {
    return fmaf(tanh_fast(0.5f * x), 0.5f, 0.5f);
}
__device__ __forceinline__ void rhs5(const float* y, const float* th, float* d) {
    float f1 = th[0] * y[0] - th[4] * y[1];
    float f2 = th[1] * y[1] - th[5] * y[2];
    float f3 = th[2] * y[2] - th[6] * y[3];
    float f4 = th[3] * y[3] - th[7] * y[4];
    d[0] = -f1; d[1] = f1 - f2; d[2] = f2 - f3; d[3] = f3 - f4; d[4] = f4;
}
__device__ __forceinline__ void mma4(float* c, const u32* a, u32 b0, u32 b1) {
    asm volatile(
        "mma.sync.aligned.m16n8k16.row.col.f32.f16.f16.f32 "
        "{%0,%1,%2,%3},{%4,%5,%6,%7},{%8,%9},{%0,%1,%2,%3};"
        : "+f"(c[0]), "+f"(c[1]), "+f"(c[2]), "+f"(c[3])
        : "r"(a[0]), "r"(a[1]), "r"(a[2]), "r"(a[3]), "r"(b0), "r"(b1));
}
__device__ __forceinline__ void ldsm4(u32* a, u32 sa) {
    asm volatile("ldmatrix.sync.aligned.m8n8.x4.shared.b16 {%0,%1,%2,%3},[%4];"
        : "=r"(a[0]), "=r"(a[1]), "=r"(a[2]), "=r"(a[3]) : "r"(sa));
}

__global__ void __launch_bounds__(THREADS, 1)
rnn_main(const float* __restrict__ y0,
         const float* __restrict__ u_seq,
         const float* __restrict__ dt_seq,
         const float* __restrict__ lift_W,
         const float* __restrict__ lift_b,
         const float* __restrict__ W_ih,
         const float* __restrict__ W_hh,
         const float* __restrict__ b_ih,
         const float* __restrict__ b_hh,
         const float* __restrict__ head_W,
         const float* __restrict__ head_b,
         const float* __restrict__ ujump,
         float* __restrict__ y_out,
         float* __restrict__ theta_out) {
    extern __shared__ char smc[];
    __half* hbuf0 = (__half*)(smc + HB0_OFF);
    __half* hbuf1 = (__half*)(smc + HB1_OFF);
    __half* x16   = (__half*)(smc + X16_OFF);
    __half* wih16 = (__half*)(smc + WIH_OFF);
    __half* hW16  = (__half*)(smc + HW_OFF);
    float*  fm    = (float*)(smc + F32_OFF);
    float* lW_s = fm;          // 256
    float* lb_s = fm + 256;    // 32
    float* hb_s = fm + 288;    // 8
    float* uj_s = fm + 296;    // 16
    float* th_s = fm + 312;    // 256

    const int t = threadIdx.x, w = t >> 5, lane = t & 31;
    const int qr = lane >> 2, qc = lane & 3;
    const int R0 = blockIdx.x * M_ROWS;
    const int wj = w * 16;
    const int j_lo = wj + qr, j_hi = j_lo + 8;
    const int lm = lane >> 3;

    // ---------------- prologue: smem staging ----------------
    for (int i = t; i < 32 * H16_P / 2; i += THREADS) {
        ((u32*)hbuf0)[i] = 0;
        ((u32*)hbuf1)[i] = 0;
    }
    for (int i = t; i < 3 * 128 * 32; i += THREADS) {
        int g = i >> 12, rem = i & 4095, jj = rem >> 5, l = rem & 31;
        wih16[g * 128 * WIH_P + jj * WIH_P + l] = __float2half_rn(W_ih[i]);
    }
    for (int i = t; i < 1024; i += THREADS) {
        int c = i >> 7, kk = i & 127;
        hW16[c * HW_P + kk] = __float2half_rn(head_W[i]);
    }
    for (int i = t; i < 256; i += THREADS) lW_s[i] = lift_W[i];
    if (t < 32) lb_s[t] = lift_b[t];
    if (t < 8)  hb_s[t] = head_b[t];
    if (t < 15) uj_s[t] = ujump[t];

    // A fragments: full W_hh (3 gates) in registers
    u32 agh[3][8][4];
    #pragma unroll
    for (int g = 0; g < 3; ++g)
        #pragma unroll
        for (int s = 0; s < 8; ++s) {
            const float* p = W_hh + (g * 128 + j_lo) * 128 + 16 * s + qc * 2;
            agh[g][s][0] = packh2(p[0], p[1]);
            agh[g][s][1] = packh2(p[1024], p[1025]);
            agh[g][s][2] = packh2(p[8], p[9]);
            agh[g][s][3] = packh2(p[1032], p[1033]);
        }
    const float bR0  = b_ih[j_lo] + b_hh[j_lo];
    const float bR1  = b_ih[j_hi] + b_hh[j_hi];
    const float bZ0  = b_ih[128 + j_lo] + b_hh[128 + j_lo];
    const float bZ1  = b_ih[128 + j_hi] + b_hh[128 + j_hi];
    const float bNI0 = b_ih[256 + j_lo], bNI1 = b_ih[256 + j_hi];
    const float bNH0 = b_hh[256 + j_lo], bNH1 = b_hh[256 + j_hi];

    u32 smb;
    asm("{ .reg .u64 tt; cvta.to.shared.u64 tt, %1; cvt.u32.u64 %0, tt; }"
        : "=r"(smb) : "l"((const void*)smc));
    const u32 wih_lane = smb + WIH_OFF +
        (u32)((wj + (lm & 1) * 8 + (lane & 7)) * WIH_P + (lm >> 1) * 8) * 2u;
    // head ldsm base: w2 -> rows 0-15, w3 -> rows 16-31
    const int tw = (w - 2) & 1;
    const u32 head_row_off =
        (u32)(((tw << 4) + (lm & 1) * 8 + (lane & 7)) * H16_P + (lm >> 1) * 8) * 2u;

    // RK4/lift state (w0: rows 0-15, w1: rows 16-31; lane<16 active)
    const int rkrow = (w << 4) + lane;   // valid w<2, lane<16
    float y[5] = {0, 0, 0, 0, 0};
    float uc0 = 0, uc1 = 0, uc2 = 0, dtc = 0;
    if (w < 2 && lane < 16) {
        #pragma unroll
        for (int i = 0; i < 5; ++i) y[i] = y0[(R0 + rkrow) * 5 + i] + 0.01f;
        const float* up = u_seq + ((size_t)(R0 + rkrow) * K_STEPS) * 3;
        uc0 = up[0]; uc1 = up[1]; uc2 = up[2];
        dtc = dt_seq[(size_t)(R0 + rkrow) * K_STEPS];
    }

    float cR[4][4], cZ[4][4], cNI[4][4], cNH[4][4];
    float hp_[4][4] = {{0,0,0,0},{0,0,0,0},{0,0,0,0},{0,0,0,0}};

    auto init_accs = [&]() {
        #pragma unroll
        for (int nt = 0; nt < 4; ++nt) {
            cR[nt][0] = bR0;  cR[nt][1] = bR0;  cR[nt][2] = bR1;  cR[nt][3] = bR1;
            cZ[nt][0] = bZ0;  cZ[nt][1] = bZ0;  cZ[nt][2] = bZ1;  cZ[nt][3] = bZ1;
            cNI[nt][0] = bNI0; cNI[nt][1] = bNI0; cNI[nt][2] = bNI1; cNI[nt][3] = bNI1;
            cNH[nt][0] = bNH0; cNH[nt][1] = bNH0; cNH[nt][2] = bNH1; cNH[nt][3] = bNH1;
        }
    };
    auto do_gh = [&](const __half* hb) {
        #pragma unroll
        for (int s = 0; s < 8; ++s) {
            #pragma unroll
            for (int nt = 0; nt < 4; ++nt) {
                const __half* hp = hb + (qr + 8 * nt) * H16_P + 16 * s + qc * 2;
                u32 b0 = *(const u32*)hp;
                u32 b1 = *(const u32*)(hp + 8);
                mma4(cR[nt],  agh[0][s], b0, b1);
                mma4(cZ[nt],  agh[1][s], b0, b1);
                mma4(cNH[nt], agh[2][s], b0, b1);
            }
        }
    };
    auto do_gi = [&]() {
        #pragma unroll
        for (int s = 0; s < 2; ++s) {
            u32 aR_[4], aZ_[4], aN_[4];
            ldsm4(aR_, wih_lane + (u32)s * 32u);
            ldsm4(aZ_, wih_lane + 10240u + (u32)s * 32u);
            ldsm4(aN_, wih_lane + 20480u + (u32)s * 32u);
            #pragma unroll
            for (int nt = 0; nt < 4; ++nt) {
                const __half* xp = x16 + (qr + 8 * nt) * X16_P + 16 * s + qc * 2;
                u32 b0 = *(const u32*)xp;
                u32 b1 = *(const u32*)(xp + 8);
                mma4(cR[nt],  aR_, b0, b1);
                mma4(cZ[nt],  aZ_, b0, b1);
                mma4(cNI[nt], aN_, b0, b1);
            }
        }
    };
    auto epilogue = [&](__half* hb) {
        #pragma unroll
        for (int nt = 0; nt < 4; ++nt) {
            int r0 = qc * 2 + 8 * nt;
            float hn[4];
            #pragma unroll
            for (int c = 0; c < 4; ++c) {
                float gr = sig_fast(cR[nt][c]);
                float gz = sig_fast(cZ[nt][c]);
                float gn = tanh_fast(fmaf(gr, cNH[nt][c], cNI[nt][c]));
                hn[c] = (1.f - gz) * gn + gz * hp_[nt][c];
                hp_[nt][c] = hn[c];
            }
            hb[r0 * H16_P + j_lo]       = __float2half_rn(hn[0]);
            hb[(r0 + 1) * H16_P + j_lo] = __float2half_rn(hn[1]);
            hb[r0 * H16_P + j_hi]       = __float2half_rn(hn[2]);
            hb[(r0 + 1) * H16_P + j_hi] = __float2half_rn(hn[3]);
        }
    };
    // lift one row entirely in-lane (y in regs)
    auto lift_row = [&](int row, float u0, float u1, float u2) {
        float f[8];
        f[0] = u0; f[1] = u1; f[2] = u2;
        #pragma unroll
        for (int i = 0; i < 5; ++i) f[3 + i] = y[i];
        #pragma unroll
        for (int lp = 0; lp < 16; ++lp) {
            int l0 = lp * 2;
            const float4* wp = (const float4*)(lW_s + l0 * 8);
            float4 wa = wp[0], wb = wp[1], wc = wp[2], wd = wp[3];
            float a0 = lb_s[l0], a1 = lb_s[l0 + 1];
            a0 = fmaf(wa.x, f[0], a0); a0 = fmaf(wa.y, f[1], a0);
            a0 = fmaf(wa.z, f[2], a0); a0 = fmaf(wa.w, f[3], a0);
            a0 = fmaf(wb.x, f[4], a0); a0 = fmaf(wb.y, f[5], a0);
            a0 = fmaf(wb.z, f[6], a0); a0 = fmaf(wb.w, f[7], a0);
            a1 = fmaf(wc.x, f[0], a1); a1 = fmaf(wc.y, f[1], a1);
            a1 = fmaf(wc.z, f[2], a1); a1 = fmaf(wc.w, f[3], a1);
            a1 = fmaf(wd.x, f[4], a1); a1 = fmaf(wd.y, f[5], a1);
            a1 = fmaf(wd.z, f[6], a1); a1 = fmaf(wd.w, f[7], a1);
            *(u32*)&x16[row * X16_P + l0] =
                packh2(a0 * sig_fast(a0), a1 * sig_fast(a1));
        }
    };

    __syncthreads();
    // pre-loop: x(0) by w0/w1 lanes, then step-0 accumulators (h16 = 0)
    if (w < 2 && lane < 16) lift_row(rkrow, uc0, uc1, uc2);
    __syncthreads();
    init_accs();
    do_gi();

    // ---------------- main loop ----------------
    // barA(__syncthreads): h(k) visible
    // bar id4 (cnt 128, w0-w3): theta ready (w2/3 arrive, w0/1 sync)
    // barB(__syncthreads): x(k+1) visible + gh reads done
    for (int k = 0; k < K_STEPS; ++k) {
        __half* hb_cur = (k & 1) ? hbuf1 : hbuf0;

        // early u/dt prefetch (LDGs in flight during epilogue)
        float un0 = 0, un1 = 0, un2 = 0, dtn = 0;
        if (w < 2 && lane < 16 && k + 1 < K_STEPS) {
            const float* up = u_seq + ((size_t)(R0 + rkrow) * K_STEPS + (k + 1)) * 3;
            un0 = up[0]; un1 = up[1]; un2 = up[2];
            dtn = dt_seq[(size_t)(R0 + rkrow) * K_STEPS + (k + 1)];
        }

        epilogue(hb_cur);                 // h(k) -> buf[k&1]
        __syncthreads();                  // A: h(k) visible

        if (w >= 2) {
            if (w < 4) {
                // head(k) on tile tw (w2: rows 0-15, w3: rows 16-31)
                float cH[4];
                cH[0] = hb_s[qc * 2]; cH[1] = hb_s[qc * 2 + 1];
                cH[2] = cH[0];        cH[3] = cH[1];
                u32 a_lane = smb + ((k & 1) ? HB1_OFF : HB0_OFF) + head_row_off;
                #pragma unroll
                for (int s = 0; s < 8; ++s) {
                    u32 a[4];
                    ldsm4(a, a_lane + (u32)s * 32u);
                    u32 b0 = *(const u32*)&hW16[qr * HW_P + 16 * s + qc * 2];
                    u32 b1 = *(const u32*)&hW16[qr * HW_P + 16 * s + 8 + qc * 2];
                    mma4(cH, a, b0, b1);
                }
                int row0 = (tw << 4) + qr, row1 = row0 + 8;
                float t00 = 0.01f + 2.99f * sig_fast(cH[0]);
                float t01 = 0.01f + 2.99f * sig_fast(cH[1]);
                float t10 = 0.01f + 2.99f * sig_fast(cH[2]);
                float t11 = 0.01f + 2.99f * sig_fast(cH[3]);
                th_s[row0 * 8 + qc * 2]     = t00;
                th_s[row0 * 8 + qc * 2 + 1] = t01;
                th_s[row1 * 8 + qc * 2]     = t10;
                th_s[row1 * 8 + qc * 2 + 1] = t11;
                size_t ob0 = (((size_t)(R0 + row0)) * K_STEPS + k) * 8 + qc * 2;
                size_t ob1 = (((size_t)(R0 + row1)) * K_STEPS + k) * 8 + qc * 2;
                theta_out[ob0] = t00; theta_out[ob0 + 1] = t01;
                theta_out[ob1] = t10; theta_out[ob1 + 1] = t11;
                BAR_ARRIVE(4, 128);        // theta ready
            }
            if (k + 1 < K_STEPS) { init_accs(); do_gh(hb_cur); }
        } else {
            // w0/w1: gh FIRST (overlaps w2/3's head), then RK4+lift
            if (k + 1 < K_STEPS) { init_accs(); do_gh(hb_cur); }
            BAR_SYNC(4, 128);              // wait theta

            if (lane < 16) {
                #pragma unroll
                for (int p = 0; p < 5; ++p)
                    y[p] += uc0 * uj_s[p] + uc1 * uj_s[5 + p] + uc2 * uj_s[10 + p];
                float th[8];
                #pragma unroll
                for (int i = 0; i < 8; ++i) th[i] = th_s[rkrow * 8 + i];
                float hs = dtc * 0.1f, hh = 0.5f * hs, h6 = hs * (1.f / 6.f);
                for (int s = 0; s < 10; ++s) {
                    float k1[5], k2[5], k3[5], k4[5], yt[5];
                    rhs5(y, th, k1);
                    #pragma unroll
                    for (int i = 0; i < 5; ++i) yt[i] = fmaf(hh, k1[i], y[i]);
                    rhs5(yt, th, k2);
                    #pragma unroll
                    for (int i = 0; i < 5; ++i) yt[i] = fmaf(hh, k2[i], y[i]);
                    rhs5(yt, th, k3);
                    #pragma unroll
                    for (int i = 0; i < 5; ++i) yt[i] = fmaf(hs, k3[i], y[i]);
                    rhs5(yt, th, k4);
                    #pragma unroll
                    for (int i = 0; i < 5; ++i) {
                        float incr = k1[i] + 2.f * k2[i] + 2.f * k3[i] + k4[i];
                        y[i] = fmaxf(fmaf(h6, incr, y[i]), 0.f);
                    }
                }
                // lift first (x on critical path), y_out STG after
                if (k + 1 < K_STEPS) {
                    lift_row(rkrow, un0, un1, un2);
                    uc0 = un0; uc1 = un1; uc2 = un2; dtc = dtn;
                }
                #pragma unroll
                for (int i = 0; i < 5; ++i)
                    y_out[(((size_t)(R0 + rkrow)) * K_STEPS + k) * 5 + i] = y[i];
            }
        }
        __syncthreads();                  // B: x(k+1) visible, gh reads done

        if (k + 1 < K_STEPS) do_gi();
    }
}

extern "C" void kernel_launch(void* const* d_in, const int* in_sizes, int n_in,
                              void* d_out, int out_size) {
    const float* y0     = (const float*)d_in[0];
    const float* u_seq  = (const float*)d_in[1];
    const float* dt_seq = (const float*)d_in[2];
    const float* lift_W = (const float*)d_in[3];
    const float* lift_b = (const float*)d_in[4];
    const float* W_ih   = (const float*)d_in[5];
    const float* W_hh   = (const float*)d_in[6];
    const float* b_ih   = (const float*)d_in[7];
    const float* b_hh   = (const float*)d_in[8];
    const float* head_W = (const float*)d_in[9];
    const float* head_b = (const float*)d_in[10];
    const float* ujump  = (const float*)d_in[11];

    float* y_out     = (float*)d_out;
    float* theta_out = y_out + (size_t)B_TOT * K_STEPS * 5;

    cudaFuncSetAttribute(rnn_main, cudaFuncAttributeMaxDynamicSharedMemorySize,
                         SMEM_TOTAL);
    rnn_main<<<B_TOT / M_ROWS, THREADS, SMEM_TOTAL>>>(
        y0, u_seq, dt_seq, lift_W, lift_b, W_ih, W_hh, b_ih, b_hh,
        head_W, head_b, ujump, y_out, theta_out);
}